// round 6
// baseline (speedup 1.0000x reference)
#include <cuda_runtime.h>
#include <math.h>

#define BATCH 64
#define Hh 512
#define Ww 512
#define NPIX (Hh * Ww)
#define NELEM (NPIX * 3)
#define MAGv 0.5f
#define ENHv (1.0f + 0.9f * MAGv)      // 1.45
#define FILLv 0.5f
#define INV_NELEM (1.0f / (float)NELEM)
#define TPB 128

// g_buf layout is per-image: interleaved HWC when op1 is pointwise,
// planar CHW (plane ch at offset ch*NPIX) when op1 is a gather op.
__device__ float g_buf[(size_t)BATCH * NELEM];
__device__ float g_sumA[BATCH];   // sum of raw input (op0 == contrast)
__device__ float g_sumB[BATCH];   // sum of layer-0 output (op1 == contrast)

__device__ __forceinline__ float clip01(float v) {
    return fminf(fmaxf(v, 0.0f), 1.0f);
}

__device__ __forceinline__ float pw0(float v, int op, float f, float m) {
    return (op == 5) ? clip01(f * v) : clip01(m + f * (v - m));
}

__device__ __forceinline__ void affineCoef(int op, float s,
        float& A, float& B, float& TX, float& C, float& D, float& TY) {
    A = 1.0f; B = 0.0f; TX = 0.0f; C = 0.0f; D = 1.0f; TY = 0.0f;
    if (op == 0) {
        float th = s * (30.0f * MAGv) * (3.14159265358979323846f / 180.0f);
        float si, co;
        sincosf(th, &si, &co);
        A = co; B = si; C = -si; D = co;
    } else if (op == 1) {
        B = -(s * 0.3f * MAGv);
    } else if (op == 2) {
        C = -(s * 0.3f * MAGv);
    } else if (op == 3) {
        TX = -(s * 0.3f * MAGv * (float)Ww);
    } else if (op == 4) {
        TY = -(s * 0.3f * MAGv * (float)Hh);
    }
}

// ---------------- prepass kernels ----------------
__global__ void zero_sums_kernel() {
    if (threadIdx.x < BATCH) {
        g_sumA[threadIdx.x] = 0.0f;
        g_sumB[threadIdx.x] = 0.0f;
    }
}

__global__ void meanA_kernel(const float* __restrict__ in, const int* __restrict__ ops) {
    const int b = blockIdx.y;
    if (__ldg(&ops[b * 2]) != 6) return;
    const float* img = in + (size_t)b * NELEM;
    float acc = 0.0f;
    const int stride = gridDim.x * blockDim.x;
    for (int i = blockIdx.x * blockDim.x + threadIdx.x; i < NELEM; i += stride)
        acc += __ldg(&img[i]);
    #pragma unroll
    for (int off = 16; off > 0; off >>= 1)
        acc += __shfl_down_sync(0xffffffffu, acc, off);
    if ((threadIdx.x & 31) == 0) atomicAdd(&g_sumA[b], acc);
}

// sum of pointwise-L0 for images with op0 in {5,6} AND op1 == contrast
__global__ void meanB_pw_kernel(const float* __restrict__ in, const int* __restrict__ ops,
                                const int* __restrict__ signs) {
    const int b = blockIdx.y;
    const int op0 = __ldg(&ops[b * 2]);
    if (!((op0 == 5 || op0 == 6) && __ldg(&ops[b * 2 + 1]) == 6)) return;
    const float s0 = 2.0f * (float)__ldg(&signs[b * 2]) - 1.0f;
    const float f0 = (s0 > 0.0f) ? ENHv : (1.0f / ENHv);
    const float m0 = g_sumA[b] * INV_NELEM;
    const float* img = in + (size_t)b * NELEM;
    float acc = 0.0f;
    const int stride = gridDim.x * blockDim.x;
    for (int i = blockIdx.x * blockDim.x + threadIdx.x; i < NELEM; i += stride)
        acc += pw0(__ldg(&img[i]), op0, f0, m0);
    #pragma unroll
    for (int off = 16; off > 0; off >>= 1)
        acc += __shfl_down_sync(0xffffffffu, acc, off);
    if ((threadIdx.x & 31) == 0) atomicAdd(&g_sumB[b], acc);
}

// ---------------- pass 1: produce L0 rows ----------------
// grid (Hh, BATCH), block 128. One block = one image row.
// Processes: op0-heavy images, plus routeA images whose op1 is a gather op
// (those get pw-planarized so pass2 always gathers from planar data).
__global__ void __launch_bounds__(TPB) pass1_kernel(
        const float* __restrict__ in, float* __restrict__ dout,
        const int* __restrict__ ops, const int* __restrict__ signs) {
    __shared__ float sp0[Ww], sp1[Ww], sp2[Ww];   // channel planes of this row

    const int b = blockIdx.y;
    const int op0 = __ldg(&ops[b * 2]);
    const int op1 = __ldg(&ops[b * 2 + 1]);
    const bool routeA = (op0 == 5 || op0 == 6);
    const bool op1gather = (op1 < 5 || op1 == 7);
    if (routeA && !op1gather) return;        // dense-dense: pass2 single-pass

    const int y = blockIdx.x;
    const int tid = threadIdx.x;
    const float s0 = 2.0f * (float)__ldg(&signs[b * 2]) - 1.0f;
    const float s1 = 2.0f * (float)__ldg(&signs[b * 2 + 1]) - 1.0f;
    const float f0 = (s0 > 0.0f) ? ENHv : (1.0f / ENHv);
    const float f1 = (s1 > 0.0f) ? ENHv : (1.0f / ENHv);
    const float m0 = g_sumA[b] * INV_NELEM;

    const float* img = in + (size_t)b * NELEM;
    const bool wantSum = (op1 == 6);         // only reachable when op0 heavy
    float acc = 0.0f;

    if (routeA) {
        // dense pw planarize: read interleaved row (f4), scatter to planes
        const float4* r4 = (const float4*)(img + y * (Ww * 3));
        for (int i = tid; i < (Ww * 3) / 4; i += TPB) {
            float4 v = __ldg(&r4[i]);
            float e[4] = { pw0(v.x, op0, f0, m0), pw0(v.y, op0, f0, m0),
                           pw0(v.z, op0, f0, m0), pw0(v.w, op0, f0, m0) };
            #pragma unroll
            for (int j = 0; j < 4; j++) {
                int ee = 4 * i + j;
                int x = ee / 3, c = ee - 3 * x;
                ((c == 0) ? sp0 : (c == 1) ? sp1 : sp2)[x] = e[j];
            }
        }
    } else if (op0 < 5) {
        float a, bb, tx, c, d, ty;
        affineCoef(op0, s0, a, bb, tx, c, d, ty);
        const float cx = 255.5f, cy = 255.5f;
        const float yb = (float)y - cy;
        const float xiB = bb * yb + tx + cx;
        const float yiB = d * yb + ty + cy;
        #pragma unroll
        for (int j = 0; j < 4; j++) {
            const int x = j * TPB + tid;
            const float xd = (float)x - cx;
            const float xi = a * xd + xiB;
            const float yi = c * xd + yiB;
            const float xf = floorf(xi), yf = floorf(yi);
            const float wx = xi - xf, wy = yi - yf;
            const int ix = (int)xf, iy = (int)yf;
            const float w00 = (1.0f - wx) * (1.0f - wy), w10 = wx * (1.0f - wy);
            const float w01 = (1.0f - wx) * wy, w11 = wx * wy;
            float r0 = 0.0f, r1 = 0.0f, r2 = 0.0f;
            #pragma unroll
            for (int t = 0; t < 4; t++) {
                const int ty2 = iy + (t >> 1), tx2 = ix + (t & 1);
                const float w = (t == 0) ? w00 : (t == 1) ? w10 : (t == 2) ? w01 : w11;
                if ((unsigned)tx2 >= (unsigned)Ww || (unsigned)ty2 >= (unsigned)Hh) {
                    r0 += w * FILLv; r1 += w * FILLv; r2 += w * FILLv;
                } else {
                    const float* p = img + (ty2 * Ww + tx2) * 3;
                    r0 += w * __ldg(p); r1 += w * __ldg(p + 1); r2 += w * __ldg(p + 2);
                }
            }
            sp0[x] = r0; sp1[x] = r1; sp2[x] = r2;
            if (wantSum) acc += r0 + r1 + r2;
        }
    } else {   // op0 == 7 : sharpness from interleaved input
        const int ym = max(y - 1, 0), yp = min(y + 1, Hh - 1);
        #pragma unroll
        for (int j = 0; j < 4; j++) {
            const int x = j * TPB + tid;
            const int xm = max(x - 1, 0), xp = min(x + 1, Ww - 1);
            const float k1 = 1.0f / 13.0f, k5 = 5.0f / 13.0f;
            #pragma unroll
            for (int ch = 0; ch < 3; ch++) {
                const float* rm = img + ym * (Ww * 3) + ch;
                const float* rc = img + y * (Ww * 3) + ch;
                const float* rp = img + yp * (Ww * 3) + ch;
                float sm = k1 * (__ldg(rm + xm * 3) + __ldg(rm + x * 3) + __ldg(rm + xp * 3)
                               + __ldg(rc + xm * 3) + __ldg(rc + xp * 3)
                               + __ldg(rp + xm * 3) + __ldg(rp + x * 3) + __ldg(rp + xp * 3))
                         + k5 * __ldg(rc + x * 3);
                float cv = __ldg(rc + x * 3);
                float v = clip01(sm + f0 * (cv - sm));
                ((ch == 0) ? sp0 : (ch == 1) ? sp1 : sp2)[x] = v;
                if (wantSum) acc += v;
            }
        }
    }
    __syncthreads();

    if (op1gather) {
        // planar writeout to g_buf (conflict-free f4)
        float* base = g_buf + (size_t)b * NELEM + y * Ww;
        float4* p0 = (float4*)(base);
        float4* p1 = (float4*)(base + NPIX);
        float4* p2 = (float4*)(base + 2 * NPIX);
        for (int i = tid; i < Ww / 4; i += TPB) {
            p0[i] = ((float4*)sp0)[i];
            p1[i] = ((float4*)sp1)[i];
            p2[i] = ((float4*)sp2)[i];
        }
    } else {
        // interleaved writeout; op1==5 folds brightness straight to dout
        const bool bright = (op1 == 5);
        float4* d4 = (float4*)((bright ? dout : g_buf) + (size_t)b * NELEM + y * (Ww * 3));
        for (int i = tid; i < (Ww * 3) / 4; i += TPB) {
            float e[4];
            #pragma unroll
            for (int j = 0; j < 4; j++) {
                int ee = 4 * i + j;
                int x = ee / 3, c = ee - 3 * x;
                float v = ((c == 0) ? sp0 : (c == 1) ? sp1 : sp2)[x];
                e[j] = bright ? clip01(f1 * v) : v;
            }
            d4[i] = make_float4(e[0], e[1], e[2], e[3]);
        }
    }

    if (wantSum) {
        #pragma unroll
        for (int off = 16; off > 0; off >>= 1)
            acc += __shfl_down_sync(0xffffffffu, acc, off);
        if ((tid & 31) == 0) atomicAdd(&g_sumB[b], acc);
    }
}

// ---------------- pass 2 ----------------
// grid (Hh, BATCH), block 128.
__global__ void __launch_bounds__(TPB) pass2_kernel(
        const float* __restrict__ in, float* __restrict__ dout,
        const int* __restrict__ ops, const int* __restrict__ signs) {
    __shared__ float srow[Ww * 3];

    const int b = blockIdx.y;
    const int op0 = __ldg(&ops[b * 2]);
    const int op1 = __ldg(&ops[b * 2 + 1]);
    const bool routeA = (op0 == 5 || op0 == 6);
    if (!routeA && op1 == 5) return;         // fully handled in pass 1

    const int y = blockIdx.x;
    const int tid = threadIdx.x;
    const float s0 = 2.0f * (float)__ldg(&signs[b * 2]) - 1.0f;
    const float s1 = 2.0f * (float)__ldg(&signs[b * 2 + 1]) - 1.0f;
    const float f0 = (s0 > 0.0f) ? ENHv : (1.0f / ENHv);
    const float f1 = (s1 > 0.0f) ? ENHv : (1.0f / ENHv);
    const float m0 = g_sumA[b] * INV_NELEM;
    float* out = dout + (size_t)b * NELEM;

    if (op1 == 5 || op1 == 6) {
        // dense elementwise (layouts match: both interleaved)
        const float m1 = g_sumB[b] * INV_NELEM;
        const float* src = (routeA ? in : g_buf) + (size_t)b * NELEM;
        const float4* s4 = (const float4*)(src + y * (Ww * 3));
        float4* d4 = (float4*)(out + y * (Ww * 3));
        for (int i = tid; i < (Ww * 3) / 4; i += TPB) {
            float4 v = __ldg(&s4[i]);
            if (routeA) {
                v.x = pw0(v.x, op0, f0, m0); v.y = pw0(v.y, op0, f0, m0);
                v.z = pw0(v.z, op0, f0, m0); v.w = pw0(v.w, op0, f0, m0);
            }
            if (op1 == 5) {
                v.x = clip01(f1 * v.x); v.y = clip01(f1 * v.y);
                v.z = clip01(f1 * v.z); v.w = clip01(f1 * v.w);
            } else {
                v.x = clip01(m1 + f1 * (v.x - m1)); v.y = clip01(m1 + f1 * (v.y - m1));
                v.z = clip01(m1 + f1 * (v.z - m1)); v.w = clip01(m1 + f1 * (v.w - m1));
            }
            d4[i] = v;
        }
        return;
    }

    // gather ops: L0 is PLANAR in g_buf for every image reaching here
    const float* base = g_buf + (size_t)b * NELEM;
    const float* pl0 = base;
    const float* pl1 = base + NPIX;
    const float* pl2 = base + 2 * NPIX;

    if (op1 < 5) {
        float a, bb, tx, c, d, ty;
        affineCoef(op1, s1, a, bb, tx, c, d, ty);
        const float cx = 255.5f, cy = 255.5f;
        const float yb = (float)y - cy;
        const float xiB = bb * yb + tx + cx;
        const float yiB = d * yb + ty + cy;
        #pragma unroll
        for (int j = 0; j < 4; j++) {
            const int x = j * TPB + tid;
            const float xd = (float)x - cx;
            const float xi = a * xd + xiB;
            const float yi = c * xd + yiB;
            const float xf = floorf(xi), yf = floorf(yi);
            const float wx = xi - xf, wy = yi - yf;
            const int ix = (int)xf, iy = (int)yf;
            const float w00 = (1.0f - wx) * (1.0f - wy), w10 = wx * (1.0f - wy);
            const float w01 = (1.0f - wx) * wy, w11 = wx * wy;
            float r0 = 0.0f, r1 = 0.0f, r2 = 0.0f;
            #pragma unroll
            for (int t = 0; t < 4; t++) {
                const int ty2 = iy + (t >> 1), tx2 = ix + (t & 1);
                const float w = (t == 0) ? w00 : (t == 1) ? w10 : (t == 2) ? w01 : w11;
                if ((unsigned)tx2 >= (unsigned)Ww || (unsigned)ty2 >= (unsigned)Hh) {
                    r0 += w * FILLv; r1 += w * FILLv; r2 += w * FILLv;
                } else {
                    const int idx = ty2 * Ww + tx2;
                    r0 += w * __ldg(pl0 + idx);
                    r1 += w * __ldg(pl1 + idx);
                    r2 += w * __ldg(pl2 + idx);
                }
            }
            srow[x * 3] = r0; srow[x * 3 + 1] = r1; srow[x * 3 + 2] = r2;
        }
    } else {   // op1 == 7 : sharpness of planar L0
        const int ym = max(y - 1, 0), yp = min(y + 1, Hh - 1);
        #pragma unroll
        for (int j = 0; j < 4; j++) {
            const int x = j * TPB + tid;
            const int xm = max(x - 1, 0), xp = min(x + 1, Ww - 1);
            const float k1 = 1.0f / 13.0f, k5 = 5.0f / 13.0f;
            #pragma unroll
            for (int ch = 0; ch < 3; ch++) {
                const float* pl = (ch == 0) ? pl0 : (ch == 1) ? pl1 : pl2;
                const float* rm = pl + ym * Ww;
                const float* rc = pl + y * Ww;
                const float* rp = pl + yp * Ww;
                float t4 = __ldg(rc + x);
                float sm = k1 * (__ldg(rm + xm) + __ldg(rm + x) + __ldg(rm + xp)
                               + __ldg(rc + xm) + __ldg(rc + xp)
                               + __ldg(rp + xm) + __ldg(rp + x) + __ldg(rp + xp))
                         + k5 * t4;
                srow[x * 3 + ch] = clip01(sm + f1 * (t4 - sm));
            }
        }
    }
    __syncthreads();

    const float4* s4 = (const float4*)srow;
    float4* d4 = (float4*)(out + y * (Ww * 3));
    for (int i = tid; i < (Ww * 3) / 4; i += TPB)
        d4[i] = s4[i];
}

extern "C" void kernel_launch(void* const* d_in, const int* in_sizes, int n_in,
                              void* d_out, int out_size) {
    const float* images = (const float*)d_in[0];
    const int* op_ids = (const int*)d_in[1];
    const int* sgn = (const int*)d_in[2];
    float* out = (float*)d_out;

    zero_sums_kernel<<<1, 64>>>();
    meanA_kernel<<<dim3(64, BATCH), 256>>>(images, op_ids);
    meanB_pw_kernel<<<dim3(64, BATCH), 256>>>(images, op_ids, sgn);
    pass1_kernel<<<dim3(Hh, BATCH), TPB>>>(images, out, op_ids, sgn);
    pass2_kernel<<<dim3(Hh, BATCH), TPB>>>(images, out, op_ids, sgn);
}